// round 4
// baseline (speedup 1.0000x reference)
#include <cuda_runtime.h>
#include <cstdint>

// IF neuron over x[T=4, B=32, H=512, W=1024] fp32:
//   per spatial position p: v=0; for t: v+=x[t][p]; s=(v>=1)?1:0; out[t][p]=s; v-=s
// Pure streaming: 268 MB in + 268 MB out. Mixed-R/W HBM ceiling ~6.3 TB/s.
// R4: R2 structure (MLP=4 float4 loads), int32 indexing, exact grid, no hints.

static constexpr int SPATIAL4 = 4194304;        // (32*512*1024)/4 float4s per t-plane
static constexpr int THREADS  = 256;
static constexpr int NBLK     = SPATIAL4 / THREADS;  // 16384, exact cover

__device__ __forceinline__ float step1(float& v, float xt) {
    v += xt;
    float s = (v >= 1.0f) ? 1.0f : 0.0f;
    v -= s;
    return s;
}

__device__ __forceinline__ void scan4(float x0, float x1, float x2, float x3,
                                      float& o0, float& o1, float& o2, float& o3) {
    float v = 0.0f;
    o0 = step1(v, x0);
    o1 = step1(v, x1);
    o2 = step1(v, x2);
    o3 = step1(v, x3);
}

__global__ __launch_bounds__(THREADS)
void if_neuron_kernel(const float4* __restrict__ x, float4* __restrict__ out) {
    int idx = blockIdx.x * THREADS + threadIdx.x;   // < 4,194,304 — int32 safe

    // 4 independent 128-bit loads, front-batched (MLP=4)
    float4 x0 = x[idx];
    float4 x1 = x[idx + SPATIAL4];
    float4 x2 = x[idx + 2 * SPATIAL4];
    float4 x3 = x[idx + 3 * SPATIAL4];

    float4 o0, o1, o2, o3;
    scan4(x0.x, x1.x, x2.x, x3.x, o0.x, o1.x, o2.x, o3.x);
    scan4(x0.y, x1.y, x2.y, x3.y, o0.y, o1.y, o2.y, o3.y);
    scan4(x0.z, x1.z, x2.z, x3.z, o0.z, o1.z, o2.z, o3.z);
    scan4(x0.w, x1.w, x2.w, x3.w, o0.w, o1.w, o2.w, o3.w);

    out[idx]                = o0;
    out[idx + SPATIAL4]     = o1;
    out[idx + 2 * SPATIAL4] = o2;
    out[idx + 3 * SPATIAL4] = o3;
}

extern "C" void kernel_launch(void* const* d_in, const int* in_sizes, int n_in,
                              void* d_out, int out_size) {
    const float4* x = (const float4*)d_in[0];
    float4* out = (float4*)d_out;
    if_neuron_kernel<<<NBLK, THREADS>>>(x, out);
}

// round 6
// speedup vs baseline: 1.0113x; 1.0113x over previous
#include <cuda_runtime.h>
#include <cstdint>

// IF neuron over x[T=4, B=32, H=512, W=1024] fp32:
//   per spatial position p: v=0; for t: v+=x[t][p]; s=(v>=1)?1:0; out[t][p]=s; v-=s
// Pure streaming: 268 MB in + 268 MB out.
// Converged at mixed-R/W HBM ceiling (~6.25 TB/s, 78% of spec) across
// MLP=4/MLP=8/int32 variants. R6 (= R5 resubmit after infra flake): same body,
// 512-thread blocks (8192 CTAs) to trim wave-quantization / launch overhead.

static constexpr int SPATIAL4 = 4194304;        // (32*512*1024)/4 float4s per t-plane
static constexpr int THREADS  = 512;
static constexpr int NBLK     = SPATIAL4 / THREADS;  // 8192, exact cover

__device__ __forceinline__ float step1(float& v, float xt) {
    v += xt;
    float s = (v >= 1.0f) ? 1.0f : 0.0f;
    v -= s;
    return s;
}

__device__ __forceinline__ void scan4(float x0, float x1, float x2, float x3,
                                      float& o0, float& o1, float& o2, float& o3) {
    float v = 0.0f;
    o0 = step1(v, x0);
    o1 = step1(v, x1);
    o2 = step1(v, x2);
    o3 = step1(v, x3);
}

__global__ __launch_bounds__(THREADS)
void if_neuron_kernel(const float4* __restrict__ x, float4* __restrict__ out) {
    int idx = blockIdx.x * THREADS + threadIdx.x;   // < 4,194,304 — int32 safe

    // 4 independent 128-bit loads, front-batched (MLP=4)
    float4 x0 = x[idx];
    float4 x1 = x[idx + SPATIAL4];
    float4 x2 = x[idx + 2 * SPATIAL4];
    float4 x3 = x[idx + 3 * SPATIAL4];

    float4 o0, o1, o2, o3;
    scan4(x0.x, x1.x, x2.x, x3.x, o0.x, o1.x, o2.x, o3.x);
    scan4(x0.y, x1.y, x2.y, x3.y, o0.y, o1.y, o2.y, o3.y);
    scan4(x0.z, x1.z, x2.z, x3.z, o0.z, o1.z, o2.z, o3.z);
    scan4(x0.w, x1.w, x2.w, x3.w, o0.w, o1.w, o2.w, o3.w);

    out[idx]                = o0;
    out[idx + SPATIAL4]     = o1;
    out[idx + 2 * SPATIAL4] = o2;
    out[idx + 3 * SPATIAL4] = o3;
}

extern "C" void kernel_launch(void* const* d_in, const int* in_sizes, int n_in,
                              void* d_out, int out_size) {
    const float4* x = (const float4*)d_in[0];
    float4* out = (float4*)d_out;
    if_neuron_kernel<<<NBLK, THREADS>>>(x, out);
}